// round 8
// baseline (speedup 1.0000x reference)
#include <cuda_runtime.h>
#include <cuda_fp16.h>
#include <cstdint>

#define B_   8
#define C_   64
#define HW_  4096
#define D_   8
#define TBN  128
#define NT   (HW_ / TBN)     // 32
#define LOG2E 1.4426950408889634f

// ---------------- device scratch (allocation-free rule) ----------------
__device__ __align__(16) __half g_qh[B_ * HW_ * D_];   // [b][n][8] fp16, pre-scaled log2e
__device__ __align__(16) __half g_kh[B_ * HW_ * D_];   // [b][m][8] fp16
__device__ __align__(16) __half g_vh[B_ * C_ * HW_];   // [b][c][n'] fp16, key-permuted

// ---------------- smem geometry (attn): V-only ring ----------------
#define VPITCH  288                   // bytes per chan row (256B data + 32 pad)
#define VBYTES  (C_ * VPITCH)         // 18432
#define SMEM_TOTAL (3 * VBYTES)       // 55296

// ---------------- helpers ----------------
__device__ __forceinline__ uint32_t smem_u32(const void* p) {
    uint32_t a;
    asm("{ .reg .u64 t; cvta.to.shared.u64 t, %1; cvt.u32.u64 %0, t; }" : "=r"(a) : "l"(p));
    return a;
}
__device__ __forceinline__ uint32_t f16x2(float hi, float lo) {  // d = {lo, hi}
    uint32_t r; asm("cvt.rn.f16x2.f32 %0, %1, %2;" : "=r"(r) : "f"(hi), "f"(lo));
    return r;
}
__device__ __forceinline__ uint32_t h2ex2(uint32_t x) {
    uint32_t r; asm("ex2.approx.f16x2 %0, %1;" : "=r"(r) : "r"(x)); return r;
}
__device__ __forceinline__ uint32_t hmax2(uint32_t a, uint32_t b) {
    uint32_t d; asm("max.f16x2 %0, %1, %2;" : "=r"(d) : "r"(a), "r"(b)); return d;
}
__device__ __forceinline__ void lds64(uint32_t& x, uint32_t& y, uint32_t a) {
    asm volatile("ld.shared.v2.b32 {%0, %1}, [%2];" : "=r"(x), "=r"(y) : "r"(a));
}
__device__ __forceinline__ void cp16(uint32_t dst, const void* src) {
    asm volatile("cp.async.cg.shared.global [%0], [%1], 16;" :: "r"(dst), "l"(src) : "memory");
}
__device__ __forceinline__ void cp_commit() {
    asm volatile("cp.async.commit_group;" ::: "memory");
}
template <int N>
__device__ __forceinline__ void cp_wait() {
    asm volatile("cp.async.wait_group %0;" :: "n"(N) : "memory");
}
// S (phase 1): m16n8k8 fp16 -> fp16 D (for max only)
__device__ __forceinline__ void mma8_h16d(uint32_t& d0, uint32_t& d1,
                                          uint32_t a0, uint32_t a1, uint32_t b0) {
    asm("mma.sync.aligned.m16n8k8.row.col.f16.f16.f16.f16 "
        "{%0,%1},{%2,%3},{%4},{%5,%6};"
        : "=r"(d0), "=r"(d1) : "r"(a0), "r"(a1), "r"(b0), "r"(0u), "r"(0u));
}
// S (phase 2): m16n8k8 fp16 -> fp32 accum
__device__ __forceinline__ void mma8_hf(float* c, uint32_t a0, uint32_t a1, uint32_t b0) {
    asm("mma.sync.aligned.m16n8k8.row.col.f32.f16.f16.f32 "
        "{%0,%1,%2,%3},{%4,%5},{%6},{%0,%1,%2,%3};"
        : "+f"(c[0]), "+f"(c[1]), "+f"(c[2]), "+f"(c[3])
        : "r"(a0), "r"(a1), "r"(b0));
}
// PV: m16n8k16 fp16 -> fp32
__device__ __forceinline__ void mma16h(float* c, const uint32_t* a, uint32_t b0, uint32_t b1) {
    asm("mma.sync.aligned.m16n8k16.row.col.f32.f16.f16.f32 "
        "{%0,%1,%2,%3},{%4,%5,%6,%7},{%8,%9},{%0,%1,%2,%3};"
        : "+f"(c[0]), "+f"(c[1]), "+f"(c[2]), "+f"(c[3])
        : "r"(a[0]), "r"(a[1]), "r"(a[2]), "r"(a[3]), "r"(b0), "r"(b1));
}

// ---------------- packed f32x2 helpers (proj) ----------------
__device__ __forceinline__ unsigned long long fma2(unsigned long long a,
                                                   unsigned long long b,
                                                   unsigned long long c) {
    unsigned long long d;
    asm("fma.rn.f32x2 %0, %1, %2, %3;" : "=l"(d) : "l"(a), "l"(b), "l"(c));
    return d;
}
__device__ __forceinline__ unsigned long long pack2(float lo, float hi) {
    unsigned long long d;
    asm("mov.b64 %0, {%1, %2};" : "=l"(d) : "f"(lo), "f"(hi));
    return d;
}
__device__ __forceinline__ void unpack2(unsigned long long v, float& lo, float& hi) {
    asm("mov.b64 {%0, %1}, %2;" : "=f"(lo), "=f"(hi) : "l"(v));
}

// key permutation within 16-groups so PV B-frags are contiguous 8B per thread
__device__ __forceinline__ int vperm(int k) {
    return (((k >> 1) & 3) << 2) | (((k >> 3) & 1) << 1) | (k & 1);
}

// ---------------- Kernel 1: 1x1-conv projections (fp16 outputs) ----------------
__global__ __launch_bounds__(256) void proj_kernel(
    const float* __restrict__ query, const float* __restrict__ value,
    const float* __restrict__ Wq, const float* __restrict__ bq,
    const float* __restrict__ Wk, const float* __restrict__ bk,
    const float* __restrict__ Wv, const float* __restrict__ bv) {
    __shared__ __align__(16) float sWqT[C_ * D_];
    __shared__ __align__(16) float sWkT[C_ * D_];
    __shared__ __align__(16) float sWvT[C_ * C_];
    __shared__ float sbq[D_], sbk[D_], sbv[C_];

    const int tid = threadIdx.x;
    for (int i = tid; i < D_ * C_; i += 256) {
        int o = i / C_, c = i % C_;
        sWqT[c * D_ + o] = Wq[i];
        sWkT[c * D_ + o] = Wk[i];
    }
    for (int i = tid; i < C_ * C_; i += 256) {
        int o = i / C_, c = i % C_;
        sWvT[c * C_ + o] = Wv[i];
    }
    if (tid < C_) sbv[tid] = bv[tid];
    if (tid < D_) { sbq[tid] = bq[tid]; sbk[tid] = bk[tid]; }
    __syncthreads();

    const int b = blockIdx.y;
    const int n = blockIdx.x * 256 + tid;
    const float* qbase = query + (size_t)b * C_ * HW_ + n;
    const float* vbase = value + (size_t)b * C_ * HW_ + n;

    float qa[D_], ka[D_];
    unsigned long long va2[C_ / 2];
#pragma unroll
    for (int d = 0; d < D_; ++d) { qa[d] = 0.f; ka[d] = 0.f; }
#pragma unroll
    for (int i = 0; i < C_ / 2; ++i) va2[i] = 0ULL;

#pragma unroll 2
    for (int c = 0; c < C_; ++c) {
        const float x = qbase[(size_t)c * HW_];
        const float y = vbase[(size_t)c * HW_];
        const float4 wq  = *(const float4*)&sWqT[c * D_];
        const float4 wq2 = *(const float4*)&sWqT[c * D_ + 4];
        const float4 wk  = *(const float4*)&sWkT[c * D_];
        const float4 wk2 = *(const float4*)&sWkT[c * D_ + 4];
        qa[0] += wq.x * x;  qa[1] += wq.y * x;  qa[2] += wq.z * x;  qa[3] += wq.w * x;
        qa[4] += wq2.x * x; qa[5] += wq2.y * x; qa[6] += wq2.z * x; qa[7] += wq2.w * x;
        ka[0] += wk.x * x;  ka[1] += wk.y * x;  ka[2] += wk.z * x;  ka[3] += wk.w * x;
        ka[4] += wk2.x * x; ka[5] += wk2.y * x; ka[6] += wk2.z * x; ka[7] += wk2.w * x;
        const unsigned long long y2 = pack2(y, y);
        const ulonglong2* wv = (const ulonglong2*)&sWvT[c * C_];
#pragma unroll
        for (int i = 0; i < C_ / 4; ++i) {
            ulonglong2 w = wv[i];
            va2[2 * i]     = fma2(w.x, y2, va2[2 * i]);
            va2[2 * i + 1] = fma2(w.y, y2, va2[2 * i + 1]);
        }
    }

    const size_t row = (size_t)b * HW_ + n;
    __half qh[8], kh[8];
#pragma unroll
    for (int d = 0; d < D_; ++d) {
        qh[d] = __float2half_rn((qa[d] + sbq[d]) * LOG2E);
        kh[d] = __float2half_rn(ka[d] + sbk[d]);
    }
    *(uint4*)&g_qh[row * D_] = *(uint4*)qh;
    *(uint4*)&g_kh[row * D_] = *(uint4*)kh;

    const int npr = (n & ~15) | vperm(n & 15);
    __half* vout = g_vh + (size_t)b * C_ * HW_ + npr;
#pragma unroll
    for (int i = 0; i < C_ / 2; ++i) {
        float lo, hi;
        unpack2(va2[i], lo, hi);
        vout[(size_t)(2 * i) * HW_]     = __float2half_rn(lo + sbv[2 * i]);
        vout[(size_t)(2 * i + 1) * HW_] = __float2half_rn(hi + sbv[2 * i + 1]);
    }
}

// ---------------- V tile loader (256 threads) ----------------
__device__ __forceinline__ void load_v(uint32_t smb, int buf, int b, int m0, int tid) {
    const uint32_t vb = smb + buf * VBYTES;
    const __half* src = g_vh + (size_t)b * C_ * HW_ + m0;
#pragma unroll
    for (int r = 0; r < 4; ++r) {
        int idx = tid + 256 * r;
        int ch = idx >> 4, sg = idx & 15;
        cp16(vb + ch * VPITCH + sg * 16, src + (size_t)ch * HW_ + sg * 8);
    }
}

// exp pack: S quads -> PV A-frag (4 regs)
__device__ __forceinline__ void expquad(uint32_t* a, const float* sA, const float* sB) {
    a[0] = h2ex2(f16x2(sA[1], sA[0]));
    a[1] = h2ex2(f16x2(sA[3], sA[2]));
    a[2] = h2ex2(f16x2(sB[1], sB[0]));
    a[3] = h2ex2(f16x2(sB[3], sB[2]));
}

// ---------------- Kernel 2: flash attention, deep-pipelined ----------------
// CTA: 256 threads, 8 warps x 16 query rows = 128 rows.  Grid: (32, 8), 2 CTAs/SM.
__global__ __launch_bounds__(256, 2) void attn_kernel(
    const float* __restrict__ value, float* __restrict__ out) {
    extern __shared__ char sm[];
    const uint32_t smb = smem_u32(sm);
    const int tid = threadIdx.x;
    const int w = tid >> 5;
    const int lane = tid & 31;
    const int g = lane >> 2;
    const int tg = lane & 3;
    const int b = blockIdx.y;
    const int n0 = blockIdx.x * 128;
    const int rbase = n0 + w * 16 + g;

    // Q A-frag (fp16 k8): 2 regs
    const uint32_t* qptr = (const uint32_t*)g_qh;
    const uint32_t qa0 = __ldg(qptr + (size_t)(b * HW_ + rbase) * 4 + tg);
    const uint32_t qa1 = __ldg(qptr + (size_t)(b * HW_ + rbase + 8) * 4 + tg);

    // start V prologue loads (overlap with phase 1)
    load_v(smb, 0, b, 0, tid);
    cp_commit();
    load_v(smb, 1, b, TBN, tid);
    cp_commit();

    // ================= Phase 1: per-row max, registers only =================
    const uint32_t* kgp = (const uint32_t*)g_kh + (size_t)b * HW_ * 4 + g * 4 + tg;
    uint32_t mh0 = 0xFC00FC00u, mh1 = 0xFC00FC00u;   // (-inf, -inf)
#pragma unroll 8
    for (int j = 0; j < HW_ / 8; ++j) {
        const uint32_t kb = __ldg(kgp + j * 32);
        uint32_t d0, d1;
        mma8_h16d(d0, d1, qa0, qa1, kb);
        mh0 = hmax2(mh0, d0);
        mh1 = hmax2(mh1, d1);
    }
    float mx0, mx1;
    {
        __half2 h0 = *reinterpret_cast<__half2*>(&mh0);
        __half2 h1 = *reinterpret_cast<__half2*>(&mh1);
        mx0 = fmaxf(__low2float(h0), __high2float(h0));
        mx1 = fmaxf(__low2float(h1), __high2float(h1));
    }
    mx0 = fmaxf(mx0, __shfl_xor_sync(0xffffffffu, mx0, 1));
    mx0 = fmaxf(mx0, __shfl_xor_sync(0xffffffffu, mx0, 2));
    mx1 = fmaxf(mx1, __shfl_xor_sync(0xffffffffu, mx1, 1));
    mx1 = fmaxf(mx1, __shfl_xor_sync(0xffffffffu, mx1, 2));

    // ================= Phase 2: softmax + PV, exp off critical path =========
    float o[8][4];
#pragma unroll
    for (int ct = 0; ct < 8; ++ct)
#pragma unroll
        for (int i = 0; i < 4; ++i) o[ct][i] = 0.f;
    float rs0 = 0.f, rs1 = 0.f;

    for (int t = 0; t < NT; ++t) {
        cp_wait<1>();
        __syncthreads();
        if (t + 2 < NT) load_v(smb, (t + 2) % 3, b, (t + 2) * TBN, tid);
        cp_commit();

        const uint32_t base = smb + (t % 3) * VBYTES;
        const uint32_t vwb  = base + g * VPITCH + tg * 8;
        const uint32_t* kt  = kgp + t * 512;   // 16 k8-groups per tile

        // ---- tile prologue: S(p0) -> a_cur; S(p1) in flight; kc = p2,p3 ----
        float sA[4], sB[4];
        uint32_t a_cur[4];
        sA[0] = -mx0; sA[1] = -mx0; sA[2] = -mx1; sA[3] = -mx1;
        sB[0] = -mx0; sB[1] = -mx0; sB[2] = -mx1; sB[3] = -mx1;
        mma8_hf(sA, qa0, qa1, __ldg(kt));
        mma8_hf(sB, qa0, qa1, __ldg(kt + 32));
        expquad(a_cur, sA, sB);
        sA[0] = -mx0; sA[1] = -mx0; sA[2] = -mx1; sA[3] = -mx1;
        sB[0] = -mx0; sB[1] = -mx0; sB[2] = -mx1; sB[3] = -mx1;
        mma8_hf(sA, qa0, qa1, __ldg(kt + 64));
        mma8_hf(sB, qa0, qa1, __ldg(kt + 96));
        uint32_t kc[2][2];
        kc[0][0] = __ldg(kt + 128); kc[0][1] = __ldg(kt + 160);   // pair 2
        kc[1][0] = __ldg(kt + 192); kc[1][1] = __ldg(kt + 224);   // pair 3

#pragma unroll
        for (int jj = 0; jj < 8; ++jj) {
            // S for pair jj+2 (K frags already resident in kc)
            float tA[4], tB[4];
            if (jj < 6) {
                tA[0] = -mx0; tA[1] = -mx0; tA[2] = -mx1; tA[3] = -mx1;
                tB[0] = -mx0; tB[1] = -mx0; tB[2] = -mx1; tB[3] = -mx1;
                mma8_hf(tA, qa0, qa1, kc[jj & 1][0]);
                mma8_hf(tB, qa0, qa1, kc[jj & 1][1]);
            }
            if (jj < 4) {  // refill freed slot with pair jj+4
                kc[jj & 1][0] = __ldg(kt + (2 * (jj + 4)) * 32);
                kc[jj & 1][1] = __ldg(kt + (2 * (jj + 4) + 1) * 32);
            }
            // V B-frags for pair jj
            uint32_t vb0[8], vb1[8];
#pragma unroll
            for (int ct = 0; ct < 8; ++ct)
                lds64(vb0[ct], vb1[ct], vwb + ct * (8 * VPITCH) + jj * 32);
            // exp for pair jj+1 (concurrent with PV below; different pipes)
            uint32_t a_next[4];
            if (jj < 7) expquad(a_next, sA, sB);
            // denom from a_cur (fp32; bias cancels with numerator)
            {
                float2 f0 = __half22float2(*reinterpret_cast<__half2*>(&a_cur[0]));
                float2 f1 = __half22float2(*reinterpret_cast<__half2*>(&a_cur[1]));
                float2 f2 = __half22float2(*reinterpret_cast<__half2*>(&a_cur[2]));
                float2 f3 = __half22float2(*reinterpret_cast<__half2*>(&a_cur[3]));
                rs0 += (f0.x + f0.y) + (f2.x + f2.y);
                rs1 += (f1.x + f1.y) + (f3.x + f3.y);
            }
            // PV for pair jj — a_cur ready since last iteration: no stall
#pragma unroll
            for (int ct = 0; ct < 8; ++ct) mma16h(o[ct], a_cur, vb0[ct], vb1[ct]);
            if (jj < 7) {
#pragma unroll
                for (int i = 0; i < 4; ++i) a_cur[i] = a_next[i];
                if (jj < 6) {
#pragma unroll
                    for (int i = 0; i < 4; ++i) { sA[i] = tA[i]; sB[i] = tB[i]; }
                }
            }
        }
    }

    // reduce row sums across tg lanes, epilogue
    rs0 += __shfl_xor_sync(0xffffffffu, rs0, 1);
    rs0 += __shfl_xor_sync(0xffffffffu, rs0, 2);
    rs1 += __shfl_xor_sync(0xffffffffu, rs1, 1);
    rs1 += __shfl_xor_sync(0xffffffffu, rs1, 2);
    const float inv0 = 1.0f / rs0;
    const float inv1 = 1.0f / rs1;

    const float* vres = value + (size_t)b * C_ * HW_;
    float* ob = out + (size_t)b * C_ * HW_;
#pragma unroll
    for (int ct = 0; ct < 8; ++ct) {
        const int ch = ct * 8 + 2 * tg;
        const size_t i00 = (size_t)ch * HW_ + rbase;
        const size_t i01 = i00 + HW_;
        const size_t i10 = i00 + 8;
        const size_t i11 = i01 + 8;
        ob[i00] = o[ct][0] * inv0 + vres[i00];
        ob[i01] = o[ct][1] * inv0 + vres[i01];
        ob[i10] = o[ct][2] * inv1 + vres[i10];
        ob[i11] = o[ct][3] * inv1 + vres[i11];
    }
}

extern "C" void kernel_launch(void* const* d_in, const int* in_sizes, int n_in,
                              void* d_out, int out_size) {
    const float* query = (const float*)d_in[0];
    const float* value = (const float*)d_in[1];
    const float* Wq    = (const float*)d_in[2];
    const float* bq    = (const float*)d_in[3];
    const float* Wk    = (const float*)d_in[4];
    const float* bk    = (const float*)d_in[5];
    const float* Wv    = (const float*)d_in[6];
    const float* bv    = (const float*)d_in[7];
    float* out = (float*)d_out;

    cudaFuncSetAttribute(attn_kernel, cudaFuncAttributeMaxDynamicSharedMemorySize,
                         SMEM_TOTAL);

    dim3 pgrid(HW_ / 256, B_);
    proj_kernel<<<pgrid, 256>>>(query, value, Wq, bq, Wk, bk, Wv, bv);
    dim3 agrid(HW_ / 128, B_);
    attn_kernel<<<agrid, 256, SMEM_TOTAL>>>(value, out);
}

// round 9
// speedup vs baseline: 1.1480x; 1.1480x over previous
#include <cuda_runtime.h>
#include <cuda_fp16.h>
#include <cuda_bf16.h>
#include <cstdint>

#define B_   8
#define C_   64
#define HW_  4096
#define D_   8
#define TBN  128
#define NT   (HW_ / TBN)     // 32
#define LOG2E 1.4426950408889634f

// ---------------- device scratch (allocation-free rule) ----------------
__device__ __align__(16) __half g_qh[B_ * HW_ * D_];          // [b][n][8] fp16, pre-scaled log2e
__device__ __align__(16) __half g_kh[B_ * HW_ * D_];          // [b][m][8] fp16
__device__ __align__(16) __nv_bfloat16 g_vb[B_ * C_ * HW_];   // [b][c][n'] bf16, key-permuted

// ---------------- smem geometry (attn): V-only ring ----------------
#define VPITCH  288                   // bytes per chan row (256B data + 32 pad)
#define VBYTES  (C_ * VPITCH)         // 18432
#define SMEM_TOTAL (3 * VBYTES)       // 55296

// ---------------- helpers ----------------
__device__ __forceinline__ uint32_t smem_u32(const void* p) {
    uint32_t a;
    asm("{ .reg .u64 t; cvta.to.shared.u64 t, %1; cvt.u32.u64 %0, t; }" : "=r"(a) : "l"(p));
    return a;
}
__device__ __forceinline__ float ex2f(float x) {
    float r; asm("ex2.approx.f32 %0, %1;" : "=f"(r) : "f"(x)); return r;
}
__device__ __forceinline__ uint32_t bf16x2(float hi, float lo) {  // d = {lo, hi}
    uint32_t r; asm("cvt.rn.bf16x2.f32 %0, %1, %2;" : "=r"(r) : "f"(hi), "f"(lo));
    return r;
}
__device__ __forceinline__ void lds64(uint32_t& x, uint32_t& y, uint32_t a) {
    asm volatile("ld.shared.v2.b32 {%0, %1}, [%2];" : "=r"(x), "=r"(y) : "r"(a));
}
__device__ __forceinline__ void cp16(uint32_t dst, const void* src) {
    asm volatile("cp.async.cg.shared.global [%0], [%1], 16;" :: "r"(dst), "l"(src) : "memory");
}
__device__ __forceinline__ void cp_commit() {
    asm volatile("cp.async.commit_group;" ::: "memory");
}
template <int N>
__device__ __forceinline__ void cp_wait() {
    asm volatile("cp.async.wait_group %0;" :: "n"(N) : "memory");
}
// S: m16n8k8 fp16 -> fp32 accum
__device__ __forceinline__ void mma8_hf(float* c, uint32_t a0, uint32_t a1, uint32_t b0) {
    asm("mma.sync.aligned.m16n8k8.row.col.f32.f16.f16.f32 "
        "{%0,%1,%2,%3},{%4,%5},{%6},{%0,%1,%2,%3};"
        : "+f"(c[0]), "+f"(c[1]), "+f"(c[2]), "+f"(c[3])
        : "r"(a0), "r"(a1), "r"(b0));
}
// PV: m16n8k16 bf16 -> fp32
__device__ __forceinline__ void mma16b(float* c, const uint32_t* a, uint32_t b0, uint32_t b1) {
    asm("mma.sync.aligned.m16n8k16.row.col.f32.bf16.bf16.f32 "
        "{%0,%1,%2,%3},{%4,%5,%6,%7},{%8,%9},{%0,%1,%2,%3};"
        : "+f"(c[0]), "+f"(c[1]), "+f"(c[2]), "+f"(c[3])
        : "r"(a[0]), "r"(a[1]), "r"(a[2]), "r"(a[3]), "r"(b0), "r"(b1));
}
// bf16x2 -> two f32 (bit shifts, ALU only)
__device__ __forceinline__ void bf2f(uint32_t p, float& lo, float& hi) {
    lo = __uint_as_float(p << 16);
    hi = __uint_as_float(p & 0xFFFF0000u);
}

// ---------------- packed f32x2 helpers (proj) ----------------
__device__ __forceinline__ unsigned long long fma2(unsigned long long a,
                                                   unsigned long long b,
                                                   unsigned long long c) {
    unsigned long long d;
    asm("fma.rn.f32x2 %0, %1, %2, %3;" : "=l"(d) : "l"(a), "l"(b), "l"(c));
    return d;
}
__device__ __forceinline__ unsigned long long pack2(float lo, float hi) {
    unsigned long long d;
    asm("mov.b64 %0, {%1, %2};" : "=l"(d) : "f"(lo), "f"(hi));
    return d;
}
__device__ __forceinline__ void unpack2(unsigned long long v, float& lo, float& hi) {
    asm("mov.b64 {%0, %1}, %2;" : "=f"(lo), "=f"(hi) : "l"(v));
}

// key permutation within 16-groups so PV B-frags are contiguous 8B per thread
__device__ __forceinline__ int vperm(int k) {
    return (((k >> 1) & 3) << 2) | (((k >> 3) & 1) << 1) | (k & 1);
}

// ---------------- Kernel 1: 1x1-conv projections ----------------
__global__ __launch_bounds__(256) void proj_kernel(
    const float* __restrict__ query, const float* __restrict__ value,
    const float* __restrict__ Wq, const float* __restrict__ bq,
    const float* __restrict__ Wk, const float* __restrict__ bk,
    const float* __restrict__ Wv, const float* __restrict__ bv) {
    __shared__ __align__(16) float sWqT[C_ * D_];
    __shared__ __align__(16) float sWkT[C_ * D_];
    __shared__ __align__(16) float sWvT[C_ * C_];
    __shared__ float sbq[D_], sbk[D_], sbv[C_];

    const int tid = threadIdx.x;
    for (int i = tid; i < D_ * C_; i += 256) {
        int o = i / C_, c = i % C_;
        sWqT[c * D_ + o] = Wq[i];
        sWkT[c * D_ + o] = Wk[i];
    }
    for (int i = tid; i < C_ * C_; i += 256) {
        int o = i / C_, c = i % C_;
        sWvT[c * C_ + o] = Wv[i];
    }
    if (tid < C_) sbv[tid] = bv[tid];
    if (tid < D_) { sbq[tid] = bq[tid]; sbk[tid] = bk[tid]; }
    __syncthreads();

    const int b = blockIdx.y;
    const int n = blockIdx.x * 256 + tid;
    const float* qbase = query + (size_t)b * C_ * HW_ + n;
    const float* vbase = value + (size_t)b * C_ * HW_ + n;

    float qa[D_], ka[D_];
    unsigned long long va2[C_ / 2];
#pragma unroll
    for (int d = 0; d < D_; ++d) { qa[d] = 0.f; ka[d] = 0.f; }
#pragma unroll
    for (int i = 0; i < C_ / 2; ++i) va2[i] = 0ULL;

#pragma unroll 2
    for (int c = 0; c < C_; ++c) {
        const float x = qbase[(size_t)c * HW_];
        const float y = vbase[(size_t)c * HW_];
        const float4 wq  = *(const float4*)&sWqT[c * D_];
        const float4 wq2 = *(const float4*)&sWqT[c * D_ + 4];
        const float4 wk  = *(const float4*)&sWkT[c * D_];
        const float4 wk2 = *(const float4*)&sWkT[c * D_ + 4];
        qa[0] += wq.x * x;  qa[1] += wq.y * x;  qa[2] += wq.z * x;  qa[3] += wq.w * x;
        qa[4] += wq2.x * x; qa[5] += wq2.y * x; qa[6] += wq2.z * x; qa[7] += wq2.w * x;
        ka[0] += wk.x * x;  ka[1] += wk.y * x;  ka[2] += wk.z * x;  ka[3] += wk.w * x;
        ka[4] += wk2.x * x; ka[5] += wk2.y * x; ka[6] += wk2.z * x; ka[7] += wk2.w * x;
        const unsigned long long y2 = pack2(y, y);
        const ulonglong2* wv = (const ulonglong2*)&sWvT[c * C_];
#pragma unroll
        for (int i = 0; i < C_ / 4; ++i) {
            ulonglong2 w = wv[i];
            va2[2 * i]     = fma2(w.x, y2, va2[2 * i]);
            va2[2 * i + 1] = fma2(w.y, y2, va2[2 * i + 1]);
        }
    }

    const size_t row = (size_t)b * HW_ + n;
    __half qh[8], kh[8];
#pragma unroll
    for (int d = 0; d < D_; ++d) {
        qh[d] = __float2half_rn((qa[d] + sbq[d]) * LOG2E);
        kh[d] = __float2half_rn(ka[d] + sbk[d]);
    }
    *(uint4*)&g_qh[row * D_] = *(uint4*)qh;
    *(uint4*)&g_kh[row * D_] = *(uint4*)kh;

    const int npr = (n & ~15) | vperm(n & 15);
    __nv_bfloat16* vout = g_vb + (size_t)b * C_ * HW_ + npr;
#pragma unroll
    for (int i = 0; i < C_ / 2; ++i) {
        float lo, hi;
        unpack2(va2[i], lo, hi);
        vout[(size_t)(2 * i) * HW_]     = __float2bfloat16_rn(lo + sbv[2 * i]);
        vout[(size_t)(2 * i + 1) * HW_] = __float2bfloat16_rn(hi + sbv[2 * i + 1]);
    }
}

// ---------------- V tile loader (256 threads) ----------------
__device__ __forceinline__ void load_v(uint32_t smb, int buf, int b, int m0, int tid) {
    const uint32_t vb = smb + buf * VBYTES;
    const __nv_bfloat16* src = g_vb + (size_t)b * C_ * HW_ + m0;
#pragma unroll
    for (int r = 0; r < 4; ++r) {
        int idx = tid + 256 * r;
        int ch = idx >> 4, sg = idx & 15;
        cp16(vb + ch * VPITCH + sg * 16, src + (size_t)ch * HW_ + sg * 8);
    }
}

// exp pack: S quads -> PV A-frag (4 bf16x2 regs); fp32 exp (range-free)
__device__ __forceinline__ void expquad(uint32_t* a, const float* sA, const float* sB) {
    a[0] = bf16x2(ex2f(sA[1]), ex2f(sA[0]));
    a[1] = bf16x2(ex2f(sA[3]), ex2f(sA[2]));
    a[2] = bf16x2(ex2f(sB[1]), ex2f(sB[0]));
    a[3] = bf16x2(ex2f(sB[3]), ex2f(sB[2]));
}

// ---------------- Kernel 2: single-pass flash attention (bf16 P, no max) ----
// CTA: 256 threads, 8 warps x 16 query rows = 128 rows.  Grid: (32, 8), 2 CTAs/SM.
__global__ __launch_bounds__(256, 2) void attn_kernel(
    const float* __restrict__ value, float* __restrict__ out) {
    extern __shared__ char sm[];
    const uint32_t smb = smem_u32(sm);
    const int tid = threadIdx.x;
    const int w = tid >> 5;
    const int lane = tid & 31;
    const int g = lane >> 2;
    const int tg = lane & 3;
    const int b = blockIdx.y;
    const int n0 = blockIdx.x * 128;
    const int rbase = n0 + w * 16 + g;

    // V prologue loads
    load_v(smb, 0, b, 0, tid);
    cp_commit();
    load_v(smb, 1, b, TBN, tid);
    cp_commit();

    // Q A-frag (fp16 k8): 2 regs
    const uint32_t* qptr = (const uint32_t*)g_qh;
    const uint32_t qa0 = __ldg(qptr + (size_t)(b * HW_ + rbase) * 4 + tg);
    const uint32_t qa1 = __ldg(qptr + (size_t)(b * HW_ + rbase + 8) * 4 + tg);

    const uint32_t* kgp = (const uint32_t*)g_kh + (size_t)b * HW_ * 4 + g * 4 + tg;

    float o[8][4];
#pragma unroll
    for (int ct = 0; ct < 8; ++ct)
#pragma unroll
        for (int i = 0; i < 4; ++i) o[ct][i] = 0.f;
    float rs0 = 0.f, rs1 = 0.f;

    for (int t = 0; t < NT; ++t) {
        cp_wait<1>();
        __syncthreads();
        if (t + 2 < NT) load_v(smb, (t + 2) % 3, b, (t + 2) * TBN, tid);
        cp_commit();

        const uint32_t base = smb + (t % 3) * VBYTES;
        const uint32_t vwb  = base + g * VPITCH + tg * 8;
        const uint32_t* kt  = kgp + t * 512;   // 16 k8-groups per tile

        // ---- tile prologue: S(p0) -> a_cur; S(p1) in flight; kc = p2,p3 ----
        float sA[4] = {0.f, 0.f, 0.f, 0.f};
        float sB[4] = {0.f, 0.f, 0.f, 0.f};
        uint32_t a_cur[4];
        mma8_hf(sA, qa0, qa1, __ldg(kt));
        mma8_hf(sB, qa0, qa1, __ldg(kt + 32));
        expquad(a_cur, sA, sB);
        sA[0] = 0.f; sA[1] = 0.f; sA[2] = 0.f; sA[3] = 0.f;
        sB[0] = 0.f; sB[1] = 0.f; sB[2] = 0.f; sB[3] = 0.f;
        mma8_hf(sA, qa0, qa1, __ldg(kt + 64));
        mma8_hf(sB, qa0, qa1, __ldg(kt + 96));
        uint32_t kc[2][2];
        kc[0][0] = __ldg(kt + 128); kc[0][1] = __ldg(kt + 160);   // pair 2
        kc[1][0] = __ldg(kt + 192); kc[1][1] = __ldg(kt + 224);   // pair 3

#pragma unroll
        for (int jj = 0; jj < 8; ++jj) {
            // S for pair jj+2 (K frags resident in kc)
            float tA[4], tB[4];
            if (jj < 6) {
                tA[0] = 0.f; tA[1] = 0.f; tA[2] = 0.f; tA[3] = 0.f;
                tB[0] = 0.f; tB[1] = 0.f; tB[2] = 0.f; tB[3] = 0.f;
                mma8_hf(tA, qa0, qa1, kc[jj & 1][0]);
                mma8_hf(tB, qa0, qa1, kc[jj & 1][1]);
            }
            if (jj < 4) {  // refill freed slot with pair jj+4
                kc[jj & 1][0] = __ldg(kt + (2 * (jj + 4)) * 32);
                kc[jj & 1][1] = __ldg(kt + (2 * (jj + 4) + 1) * 32);
            }
            // V B-frags for pair jj (bf16, contiguous 8B per thread)
            uint32_t vb0[8], vb1[8];
#pragma unroll
            for (int ct = 0; ct < 8; ++ct)
                lds64(vb0[ct], vb1[ct], vwb + ct * (8 * VPITCH) + jj * 32);
            // exp for pair jj+1 (off critical path)
            uint32_t a_next[4];
            if (jj < 7) expquad(a_next, sA, sB);
            // denom from a_cur (bf16 -> f32 via shifts; bias cancels)
            {
                float l0, h0, l1, h1, l2, h2, l3, h3;
                bf2f(a_cur[0], l0, h0);
                bf2f(a_cur[1], l1, h1);
                bf2f(a_cur[2], l2, h2);
                bf2f(a_cur[3], l3, h3);
                rs0 += (l0 + h0) + (l2 + h2);
                rs1 += (l1 + h1) + (l3 + h3);
            }
            // PV for pair jj — a_cur ready since last iteration
#pragma unroll
            for (int ct = 0; ct < 8; ++ct) mma16b(o[ct], a_cur, vb0[ct], vb1[ct]);
            if (jj < 7) {
#pragma unroll
                for (int i = 0; i < 4; ++i) a_cur[i] = a_next[i];
                if (jj < 6) {
#pragma unroll
                    for (int i = 0; i < 4; ++i) { sA[i] = tA[i]; sB[i] = tB[i]; }
                }
            }
        }
    }

    // reduce row sums across tg lanes, epilogue
    rs0 += __shfl_xor_sync(0xffffffffu, rs0, 1);
    rs0 += __shfl_xor_sync(0xffffffffu, rs0, 2);
    rs1 += __shfl_xor_sync(0xffffffffu, rs1, 1);
    rs1 += __shfl_xor_sync(0xffffffffu, rs1, 2);
    const float inv0 = 1.0f / rs0;
    const float inv1 = 1.0f / rs1;

    const float* vres = value + (size_t)b * C_ * HW_;
    float* ob = out + (size_t)b * C_ * HW_;
#pragma unroll
    for (int ct = 0; ct < 8; ++ct) {
        const int ch = ct * 8 + 2 * tg;
        const size_t i00 = (size_t)ch * HW_ + rbase;
        const size_t i01 = i00 + HW_;
        const size_t i10 = i00 + 8;
        const size_t i11 = i01 + 8;
        ob[i00] = o[ct][0] * inv0 + vres[i00];
        ob[i01] = o[ct][1] * inv0 + vres[i01];
        ob[i10] = o[ct][2] * inv1 + vres[i10];
        ob[i11] = o[ct][3] * inv1 + vres[i11];
    }
}

extern "C" void kernel_launch(void* const* d_in, const int* in_sizes, int n_in,
                              void* d_out, int out_size) {
    const float* query = (const float*)d_in[0];
    const float* value = (const float*)d_in[1];
    const float* Wq    = (const float*)d_in[2];
    const float* bq    = (const float*)d_in[3];
    const float* Wk    = (const float*)d_in[4];
    const float* bk    = (const float*)d_in[5];
    const float* Wv    = (const float*)d_in[6];
    const float* bv    = (const float*)d_in[7];
    float* out = (float*)d_out;

    cudaFuncSetAttribute(attn_kernel, cudaFuncAttributeMaxDynamicSharedMemorySize,
                         SMEM_TOTAL);

    dim3 pgrid(HW_ / 256, B_);
    proj_kernel<<<pgrid, 256>>>(query, value, Wq, bq, Wk, bk, Wv, bv);
    dim3 agrid(HW_ / 128, B_);
    attn_kernel<<<agrid, 256, SMEM_TOTAL>>>(value, out);
}

// round 10
// speedup vs baseline: 1.1730x; 1.0218x over previous
#include <cuda_runtime.h>
#include <cuda_fp16.h>
#include <cuda_bf16.h>
#include <cstdint>

#define B_   8
#define C_   64
#define HW_  4096
#define D_   8
#define TBN  128
#define NT   (HW_ / TBN)     // 32
#define LOG2E 1.4426950408889634f
#define ONES2 0x3F803F80u    // bf16x2 {1.0, 1.0}

// ---------------- device scratch (allocation-free rule) ----------------
__device__ __align__(16) __half g_qh[B_ * HW_ * D_];          // [b][n][8] fp16, pre-scaled log2e
__device__ __align__(16) __half g_kh[B_ * HW_ * D_];          // [b][m][8] fp16
__device__ __align__(16) __nv_bfloat16 g_vb[B_ * C_ * HW_];   // [b][c][n'] bf16, key-permuted

// ---------------- smem geometry (attn): V-only ring ----------------
#define VPITCH  288                   // bytes per chan row (256B data + 32 pad)
#define VBYTES  (C_ * VPITCH)         // 18432
#define SMEM_TOTAL (3 * VBYTES)       // 55296

// ---------------- helpers ----------------
__device__ __forceinline__ uint32_t smem_u32(const void* p) {
    uint32_t a;
    asm("{ .reg .u64 t; cvta.to.shared.u64 t, %1; cvt.u32.u64 %0, t; }" : "=r"(a) : "l"(p));
    return a;
}
__device__ __forceinline__ float ex2f(float x) {
    float r; asm("ex2.approx.f32 %0, %1;" : "=f"(r) : "f"(x)); return r;
}
__device__ __forceinline__ uint32_t bf16x2(float hi, float lo) {  // d = {lo, hi}
    uint32_t r; asm("cvt.rn.bf16x2.f32 %0, %1, %2;" : "=r"(r) : "f"(hi), "f"(lo));
    return r;
}
__device__ __forceinline__ void lds64(uint32_t& x, uint32_t& y, uint32_t a) {
    asm volatile("ld.shared.v2.b32 {%0, %1}, [%2];" : "=r"(x), "=r"(y) : "r"(a));
}
__device__ __forceinline__ void cp16(uint32_t dst, const void* src) {
    asm volatile("cp.async.cg.shared.global [%0], [%1], 16;" :: "r"(dst), "l"(src) : "memory");
}
__device__ __forceinline__ void cp_commit() {
    asm volatile("cp.async.commit_group;" ::: "memory");
}
template <int N>
__device__ __forceinline__ void cp_wait() {
    asm volatile("cp.async.wait_group %0;" :: "n"(N) : "memory");
}
// S: m16n8k8 fp16 -> fp32 accum
__device__ __forceinline__ void mma8_hf(float* c, uint32_t a0, uint32_t a1, uint32_t b0) {
    asm("mma.sync.aligned.m16n8k8.row.col.f32.f16.f16.f32 "
        "{%0,%1,%2,%3},{%4,%5},{%6},{%0,%1,%2,%3};"
        : "+f"(c[0]), "+f"(c[1]), "+f"(c[2]), "+f"(c[3])
        : "r"(a0), "r"(a1), "r"(b0));
}
// PV: m16n8k16 bf16 -> fp32
__device__ __forceinline__ void mma16b(float* c, const uint32_t* a, uint32_t b0, uint32_t b1) {
    asm("mma.sync.aligned.m16n8k16.row.col.f32.bf16.bf16.f32 "
        "{%0,%1,%2,%3},{%4,%5,%6,%7},{%8,%9},{%0,%1,%2,%3};"
        : "+f"(c[0]), "+f"(c[1]), "+f"(c[2]), "+f"(c[3])
        : "r"(a[0]), "r"(a[1]), "r"(a[2]), "r"(a[3]), "r"(b0), "r"(b1));
}

// ---------------- packed f32x2 helpers (proj) ----------------
__device__ __forceinline__ unsigned long long fma2(unsigned long long a,
                                                   unsigned long long b,
                                                   unsigned long long c) {
    unsigned long long d;
    asm("fma.rn.f32x2 %0, %1, %2, %3;" : "=l"(d) : "l"(a), "l"(b), "l"(c));
    return d;
}
__device__ __forceinline__ unsigned long long pack2(float lo, float hi) {
    unsigned long long d;
    asm("mov.b64 %0, {%1, %2};" : "=l"(d) : "f"(lo), "f"(hi));
    return d;
}
__device__ __forceinline__ void unpack2(unsigned long long v, float& lo, float& hi) {
    asm("mov.b64 {%0, %1}, %2;" : "=f"(lo), "=f"(hi) : "l"(v));
}

// key permutation within 16-groups so PV B-frags are contiguous 8B per thread
__device__ __forceinline__ int vperm(int k) {
    return (((k >> 1) & 3) << 2) | (((k >> 3) & 1) << 1) | (k & 1);
}

// ---------------- Kernel 1: 1x1-conv projections ----------------
__global__ __launch_bounds__(256) void proj_kernel(
    const float* __restrict__ query, const float* __restrict__ value,
    const float* __restrict__ Wq, const float* __restrict__ bq,
    const float* __restrict__ Wk, const float* __restrict__ bk,
    const float* __restrict__ Wv, const float* __restrict__ bv) {
    __shared__ __align__(16) float sWqT[C_ * D_];
    __shared__ __align__(16) float sWkT[C_ * D_];
    __shared__ __align__(16) float sWvT[C_ * C_];
    __shared__ float sbq[D_], sbk[D_], sbv[C_];

    const int tid = threadIdx.x;
    for (int i = tid; i < D_ * C_; i += 256) {
        int o = i / C_, c = i % C_;
        sWqT[c * D_ + o] = Wq[i];
        sWkT[c * D_ + o] = Wk[i];
    }
    for (int i = tid; i < C_ * C_; i += 256) {
        int o = i / C_, c = i % C_;
        sWvT[c * C_ + o] = Wv[i];
    }
    if (tid < C_) sbv[tid] = bv[tid];
    if (tid < D_) { sbq[tid] = bq[tid]; sbk[tid] = bk[tid]; }
    __syncthreads();

    const int b = blockIdx.y;
    const int n = blockIdx.x * 256 + tid;
    const float* qbase = query + (size_t)b * C_ * HW_ + n;
    const float* vbase = value + (size_t)b * C_ * HW_ + n;

    float qa[D_], ka[D_];
    unsigned long long va2[C_ / 2];
#pragma unroll
    for (int d = 0; d < D_; ++d) { qa[d] = 0.f; ka[d] = 0.f; }
#pragma unroll
    for (int i = 0; i < C_ / 2; ++i) va2[i] = 0ULL;

#pragma unroll 2
    for (int c = 0; c < C_; ++c) {
        const float x = qbase[(size_t)c * HW_];
        const float y = vbase[(size_t)c * HW_];
        const float4 wq  = *(const float4*)&sWqT[c * D_];
        const float4 wq2 = *(const float4*)&sWqT[c * D_ + 4];
        const float4 wk  = *(const float4*)&sWkT[c * D_];
        const float4 wk2 = *(const float4*)&sWkT[c * D_ + 4];
        qa[0] += wq.x * x;  qa[1] += wq.y * x;  qa[2] += wq.z * x;  qa[3] += wq.w * x;
        qa[4] += wq2.x * x; qa[5] += wq2.y * x; qa[6] += wq2.z * x; qa[7] += wq2.w * x;
        ka[0] += wk.x * x;  ka[1] += wk.y * x;  ka[2] += wk.z * x;  ka[3] += wk.w * x;
        ka[4] += wk2.x * x; ka[5] += wk2.y * x; ka[6] += wk2.z * x; ka[7] += wk2.w * x;
        const unsigned long long y2 = pack2(y, y);
        const ulonglong2* wv = (const ulonglong2*)&sWvT[c * C_];
#pragma unroll
        for (int i = 0; i < C_ / 4; ++i) {
            ulonglong2 w = wv[i];
            va2[2 * i]     = fma2(w.x, y2, va2[2 * i]);
            va2[2 * i + 1] = fma2(w.y, y2, va2[2 * i + 1]);
        }
    }

    const size_t row = (size_t)b * HW_ + n;
    __half qh[8], kh[8];
#pragma unroll
    for (int d = 0; d < D_; ++d) {
        qh[d] = __float2half_rn((qa[d] + sbq[d]) * LOG2E);
        kh[d] = __float2half_rn(ka[d] + sbk[d]);
    }
    *(uint4*)&g_qh[row * D_] = *(uint4*)qh;
    *(uint4*)&g_kh[row * D_] = *(uint4*)kh;

    const int npr = (n & ~15) | vperm(n & 15);
    __nv_bfloat16* vout = g_vb + (size_t)b * C_ * HW_ + npr;
#pragma unroll
    for (int i = 0; i < C_ / 2; ++i) {
        float lo, hi;
        unpack2(va2[i], lo, hi);
        vout[(size_t)(2 * i) * HW_]     = __float2bfloat16_rn(lo + sbv[2 * i]);
        vout[(size_t)(2 * i + 1) * HW_] = __float2bfloat16_rn(hi + sbv[2 * i + 1]);
    }
}

// ---------------- V tile loader (256 threads) ----------------
__device__ __forceinline__ void load_v(uint32_t smb, int buf, int b, int m0, int tid) {
    const uint32_t vb = smb + buf * VBYTES;
    const __nv_bfloat16* src = g_vb + (size_t)b * C_ * HW_ + m0;
#pragma unroll
    for (int r = 0; r < 4; ++r) {
        int idx = tid + 256 * r;
        int ch = idx >> 4, sg = idx & 15;
        cp16(vb + ch * VPITCH + sg * 16, src + (size_t)ch * HW_ + sg * 8);
    }
}

// exp pack: S quads -> PV A-frag (4 bf16x2 regs); fp32 exp (range-free)
__device__ __forceinline__ void expquad(uint32_t* a, const float* sA, const float* sB) {
    a[0] = bf16x2(ex2f(sA[1]), ex2f(sA[0]));
    a[1] = bf16x2(ex2f(sA[3]), ex2f(sA[2]));
    a[2] = bf16x2(ex2f(sB[1]), ex2f(sB[0]));
    a[3] = bf16x2(ex2f(sB[3]), ex2f(sB[2]));
}

// ---------------- Kernel 2: single-pass flash attention (bf16 P) -----------
// Denominator computed ON the tensor pipe: dacc += P . 1 (ones B-frag).
// CTA: 256 threads, 8 warps x 16 query rows = 128 rows.  Grid: (32, 8), 2 CTAs/SM.
__global__ __launch_bounds__(256, 2) void attn_kernel(
    const float* __restrict__ value, float* __restrict__ out) {
    extern __shared__ char sm[];
    const uint32_t smb = smem_u32(sm);
    const int tid = threadIdx.x;
    const int w = tid >> 5;
    const int lane = tid & 31;
    const int g = lane >> 2;
    const int tg = lane & 3;
    const int b = blockIdx.y;
    const int n0 = blockIdx.x * 128;
    const int rbase = n0 + w * 16 + g;

    // V prologue loads
    load_v(smb, 0, b, 0, tid);
    cp_commit();
    load_v(smb, 1, b, TBN, tid);
    cp_commit();

    // Q A-frag (fp16 k8): 2 regs
    const uint32_t* qptr = (const uint32_t*)g_qh;
    const uint32_t qa0 = __ldg(qptr + (size_t)(b * HW_ + rbase) * 4 + tg);
    const uint32_t qa1 = __ldg(qptr + (size_t)(b * HW_ + rbase + 8) * 4 + tg);

    const uint32_t* kgp = (const uint32_t*)g_kh + (size_t)b * HW_ * 4 + g * 4 + tg;

    float o[8][4];
#pragma unroll
    for (int ct = 0; ct < 8; ++ct)
#pragma unroll
        for (int i = 0; i < 4; ++i) o[ct][i] = 0.f;
    float dacc[4] = {0.f, 0.f, 0.f, 0.f};   // row-sum accumulator (P . 1)

    for (int t = 0; t < NT; ++t) {
        cp_wait<1>();
        __syncthreads();
        if (t + 2 < NT) load_v(smb, (t + 2) % 3, b, (t + 2) * TBN, tid);
        cp_commit();

        const uint32_t base = smb + (t % 3) * VBYTES;
        const uint32_t vwb  = base + g * VPITCH + tg * 8;
        const uint32_t* kt  = kgp + t * 512;   // 16 k8-groups per tile

        // ---- tile prologue: S(p0) -> a_cur; S(p1) in flight; kc = p2,p3 ----
        float sA[4] = {0.f, 0.f, 0.f, 0.f};
        float sB[4] = {0.f, 0.f, 0.f, 0.f};
        uint32_t a_cur[4];
        mma8_hf(sA, qa0, qa1, __ldg(kt));
        mma8_hf(sB, qa0, qa1, __ldg(kt + 32));
        expquad(a_cur, sA, sB);
        sA[0] = 0.f; sA[1] = 0.f; sA[2] = 0.f; sA[3] = 0.f;
        sB[0] = 0.f; sB[1] = 0.f; sB[2] = 0.f; sB[3] = 0.f;
        mma8_hf(sA, qa0, qa1, __ldg(kt + 64));
        mma8_hf(sB, qa0, qa1, __ldg(kt + 96));
        uint32_t kc[2][2];
        kc[0][0] = __ldg(kt + 128); kc[0][1] = __ldg(kt + 160);   // pair 2
        kc[1][0] = __ldg(kt + 192); kc[1][1] = __ldg(kt + 224);   // pair 3

#pragma unroll
        for (int jj = 0; jj < 8; ++jj) {
            // S for pair jj+2 (K frags resident in kc)
            float tA[4], tB[4];
            if (jj < 6) {
                tA[0] = 0.f; tA[1] = 0.f; tA[2] = 0.f; tA[3] = 0.f;
                tB[0] = 0.f; tB[1] = 0.f; tB[2] = 0.f; tB[3] = 0.f;
                mma8_hf(tA, qa0, qa1, kc[jj & 1][0]);
                mma8_hf(tB, qa0, qa1, kc[jj & 1][1]);
            }
            if (jj < 4) {  // refill freed slot with pair jj+4
                kc[jj & 1][0] = __ldg(kt + (2 * (jj + 4)) * 32);
                kc[jj & 1][1] = __ldg(kt + (2 * (jj + 4) + 1) * 32);
            }
            // V B-frags for pair jj (bf16, contiguous 8B per thread)
            uint32_t vb0[8], vb1[8];
#pragma unroll
            for (int ct = 0; ct < 8; ++ct)
                lds64(vb0[ct], vb1[ct], vwb + ct * (8 * VPITCH) + jj * 32);
            // exp for pair jj+1 (off critical path)
            uint32_t a_next[4];
            if (jj < 7) expquad(a_next, sA, sB);
            // denominator on the tensor pipe: dacc += P . 1
            mma16b(dacc, a_cur, ONES2, ONES2);
            // PV for pair jj — a_cur ready since last iteration
#pragma unroll
            for (int ct = 0; ct < 8; ++ct) mma16b(o[ct], a_cur, vb0[ct], vb1[ct]);
            if (jj < 7) {
#pragma unroll
                for (int i = 0; i < 4; ++i) a_cur[i] = a_next[i];
                if (jj < 6) {
#pragma unroll
                    for (int i = 0; i < 4; ++i) { sA[i] = tA[i]; sB[i] = tB[i]; }
                }
            }
        }
    }

    // dacc[0] = full row sum (row g), dacc[2] = row g+8 — no reduction needed
    const float inv0 = 1.0f / dacc[0];
    const float inv1 = 1.0f / dacc[2];

    const float* vres = value + (size_t)b * C_ * HW_;
    float* ob = out + (size_t)b * C_ * HW_;
#pragma unroll
    for (int ct = 0; ct < 8; ++ct) {
        const int ch = ct * 8 + 2 * tg;
        const size_t i00 = (size_t)ch * HW_ + rbase;
        const size_t i01 = i00 + HW_;
        const size_t i10 = i00 + 8;
        const size_t i11 = i01 + 8;
        ob[i00] = o[ct][0] * inv0 + vres[i00];
        ob[i01] = o[ct][1] * inv0 + vres[i01];
        ob[i10] = o[ct][2] * inv1 + vres[i10];
        ob[i11] = o[ct][3] * inv1 + vres[i11];
    }
}

extern "C" void kernel_launch(void* const* d_in, const int* in_sizes, int n_in,
                              void* d_out, int out_size) {
    const float* query = (const float*)d_in[0];
    const float* value = (const float*)d_in[1];
    const float* Wq    = (const float*)d_in[2];
    const float* bq    = (const float*)d_in[3];
    const float* Wk    = (const float*)d_in[4];
    const float* bk    = (const float*)d_in[5];
    const float* Wv    = (const float*)d_in[6];
    const float* bv    = (const float*)d_in[7];
    float* out = (float*)d_out;

    cudaFuncSetAttribute(attn_kernel, cudaFuncAttributeMaxDynamicSharedMemorySize,
                         SMEM_TOTAL);

    dim3 pgrid(HW_ / 256, B_);
    proj_kernel<<<pgrid, 256>>>(query, value, Wq, bq, Wk, bk, Wv, bv);
    dim3 agrid(HW_ / 128, B_);
    attn_kernel<<<agrid, 256, SMEM_TOTAL>>>(value, out);
}